// round 10
// baseline (speedup 1.0000x reference)
#include <cuda_runtime.h>
#include <cuda_fp16.h>
#include <cstdint>

// GeluAvgEmbed: out[cell] = dot(gelu(mean_t W[x[cell,t]]), w_pred) + b_pred
// B,R,C,T = 8,100,64,32 ; D = 128 ; VOCAB = 32000
//
// R10: fp16 table, 2 rows per warp-iteration.
// Lanes 0-15 serve token 2i, lanes 16-31 serve token 2i+1. Each lane owns
// 8 dims of its row via one LDG.128 (4 half2). 2-way split HADD2 accumulators
// (8-add chains); split-combine and cross-half-warp fold in fp32.

#define TOKENS 32
#define DIMS   128
#define VOCAB  32000
#define FULL_MASK 0xffffffffu

// fp16 copy of the embedding table: 32000 * 128 * 2B = 8.192 MB
__device__ __half2 W_half[(size_t)VOCAB * DIMS / 2];

__global__ __launch_bounds__(256) void convert_w_kernel(
    const float* __restrict__ W, int n8)
{
    int i = blockIdx.x * blockDim.x + threadIdx.x;
    if (i >= n8) return;
    const float4* src = reinterpret_cast<const float4*>(W) + 2 * (size_t)i;
    float4 v0 = src[0];
    float4 v1 = src[1];
    __half2* dst = W_half + 4 * (size_t)i;
    dst[0] = __floats2half2_rn(v0.x, v0.y);
    dst[1] = __floats2half2_rn(v0.z, v0.w);
    dst[2] = __floats2half2_rn(v1.x, v1.y);
    dst[3] = __floats2half2_rn(v1.z, v1.w);
}

__global__ __launch_bounds__(256) void gelu_avg_embed_kernel(
    const int*   __restrict__ x,        // [n_cells * 32]
    const float* __restrict__ w_pred,   // [128]
    const float* __restrict__ b_pred,   // [1]
    float*       __restrict__ out,      // [n_cells]
    int n_cells)
{
    const int gwarp = (blockIdx.x * blockDim.x + threadIdx.x) >> 5;
    const int lane  = threadIdx.x & 31;
    if (gwarp >= n_cells) return;

    // Lane t holds token t's vocab index (coalesced 128B load of 32 ints).
    const int my_idx = x[gwarp * TOKENS + lane];

    const int half_sel = lane >> 4;   // which token of the pair this lane serves
    const int sub      = lane & 15;   // which 8-dim slice of the row

    // acc[s][j]: split s (by iteration parity), half2 j covers dims
    // (8*sub + 2j, 8*sub + 2j + 1). Each half chain sees 8 adds.
    __half2 acc[2][4];
    #pragma unroll
    for (int s = 0; s < 2; ++s)
        #pragma unroll
        for (int j = 0; j < 4; ++j)
            acc[s][j] = __float2half2_rn(0.f);

    // Lane's slice starts at half2 column 4*sub (dims 8*sub .. 8*sub+7).
    const __half2* base = W_half + 4 * (size_t)sub;

    #pragma unroll
    for (int i = 0; i < TOKENS / 2; ++i) {
        const int row = __shfl_sync(FULL_MASK, my_idx, 2 * i + half_sel);
        // 16-byte vector load: 4 half2 = 8 dims.
        float4 raw = *reinterpret_cast<const float4*>(base + (size_t)row * (DIMS / 2));
        const __half2 v0 = *reinterpret_cast<const __half2*>(&raw.x);
        const __half2 v1 = *reinterpret_cast<const __half2*>(&raw.y);
        const __half2 v2 = *reinterpret_cast<const __half2*>(&raw.z);
        const __half2 v3 = *reinterpret_cast<const __half2*>(&raw.w);
        const int s = i & 1;
        acc[s][0] = __hadd2(acc[s][0], v0);
        acc[s][1] = __hadd2(acc[s][1], v1);
        acc[s][2] = __hadd2(acc[s][2], v2);
        acc[s][3] = __hadd2(acc[s][3], v3);
    }

    // Combine splits in fp32: 8 floats per lane (dims 8*sub .. 8*sub+7),
    // currently holding this half-warp's 16-token partial sum.
    float sum[8];
    #pragma unroll
    for (int j = 0; j < 4; ++j) {
        float2 a = __half22float2(acc[0][j]);
        float2 b = __half22float2(acc[1][j]);
        sum[2 * j]     = a.x + b.x;
        sum[2 * j + 1] = a.y + b.y;
    }

    // Fold odd-token half (lanes 16-31) into even-token half (lanes 0-15).
    #pragma unroll
    for (int k = 0; k < 8; ++k)
        sum[k] += __shfl_down_sync(FULL_MASK, sum[k], 16);

    // Lanes 0-15 now hold full 32-token sums. Epilogue (all lanes execute;
    // only lanes 0-15 carry valid data into the final reduction).
    const float inv_t = 1.0f / (float)TOKENS;
    const float kInvSqrt2 = 0.70710678118654752440f;

    const float4 w0 = *reinterpret_cast<const float4*>(w_pred + sub * 8);
    const float4 w1 = *reinterpret_cast<const float4*>(w_pred + sub * 8 + 4);
    const float wv[8] = { w0.x, w0.y, w0.z, w0.w, w1.x, w1.y, w1.z, w1.w };

    float dot = 0.f;
    #pragma unroll
    for (int k = 0; k < 8; ++k) {
        const float p = sum[k] * inv_t;
        const float g = 0.5f * p * (1.0f + erff(p * kInvSqrt2));
        dot += g * wv[k];
    }

    // Reduce over the 16 valid lanes.
    #pragma unroll
    for (int off = 8; off > 0; off >>= 1)
        dot += __shfl_down_sync(FULL_MASK, dot, off);

    if (lane == 0)
        out[gwarp] = dot + b_pred[0];
}

extern "C" void kernel_launch(void* const* d_in, const int* in_sizes, int n_in,
                              void* d_out, int out_size)
{
    const int*   x      = (const int*)  d_in[0];  // [8,100,64,32] int32
    const float* W      = (const float*)d_in[1];  // [32000,128]  f32
    const float* w_pred = (const float*)d_in[2];  // [1,128]      f32
    const float* b_pred = (const float*)d_in[3];  // [1]          f32
    float*       out    = (float*)d_out;          // [8,100,64]   f32

    // 1) Convert W to fp16 scratch (8 elems per thread).
    const int n8 = VOCAB * DIMS / 8;               // 512,000
    convert_w_kernel<<<(n8 + 255) / 256, 256>>>(W, n8);

    // 2) Gather + pool + GELU + dot.
    const int n_cells = out_size;                  // 51200
    const int blocks = (n_cells + 7) / 8;          // 8 warps / block
    gelu_avg_embed_kernel<<<blocks, 256>>>(x, w_pred, b_pred, out, n_cells);
}

// round 11
// speedup vs baseline: 1.0577x; 1.0577x over previous
#include <cuda_runtime.h>
#include <cuda_fp16.h>
#include <cstdint>
#include <cstring>

// GeluAvgEmbed: out[cell] = dot(gelu(mean_t W[x[cell,t]]), w_pred) + b_pred
// B,R,C,T = 8,100,64,32 ; D = 128 ; VOCAB = 32000
//
// R11: fp16 table; 2 rows per warp-iteration (lanes 0-15 token 2i, lanes
// 16-31 token 2i+1; each lane LDG.128 = 8 dims). After the cross-half fold,
// sums are REDISTRIBUTED so every lane owns 4 dims -> 4 erffs/lane on all
// 32 lanes (the R9 epilogue shape, which R10 lost).

#define TOKENS 32
#define DIMS   128
#define VOCAB  32000
#define FULL_MASK 0xffffffffu

// fp16 copy of the embedding table: 32000 * 128 * 2B = 8.192 MB
__device__ __half2 W_half[(size_t)VOCAB * DIMS / 2];

__global__ __launch_bounds__(256) void convert_w_kernel(
    const float* __restrict__ W, int n8)
{
    int i = blockIdx.x * blockDim.x + threadIdx.x;
    if (i >= n8) return;
    const float4* src = reinterpret_cast<const float4*>(W) + 2 * (size_t)i;
    float4 v0 = src[0];
    float4 v1 = src[1];
    __half2 h[4];
    h[0] = __floats2half2_rn(v0.x, v0.y);
    h[1] = __floats2half2_rn(v0.z, v0.w);
    h[2] = __floats2half2_rn(v1.x, v1.y);
    h[3] = __floats2half2_rn(v1.z, v1.w);
    float4 packed;
    memcpy(&packed, h, 16);
    reinterpret_cast<float4*>(W_half)[i] = packed;   // one STG.128
}

__global__ __launch_bounds__(256) void gelu_avg_embed_kernel(
    const int*   __restrict__ x,        // [n_cells * 32]
    const float* __restrict__ w_pred,   // [128]
    const float* __restrict__ b_pred,   // [1]
    float*       __restrict__ out,      // [n_cells]
    int n_cells)
{
    const int gwarp = (blockIdx.x * blockDim.x + threadIdx.x) >> 5;
    const int lane  = threadIdx.x & 31;
    if (gwarp >= n_cells) return;

    // Lane t holds token t's vocab index (coalesced 128B load of 32 ints).
    const int my_idx = x[gwarp * TOKENS + lane];

    const int half_sel = lane >> 4;   // which token of the pair this lane serves
    const int sub      = lane & 15;   // which 8-dim slice of the row

    // acc[s][j]: split s = iteration parity (compile-time after unroll),
    // half2 j covers dims (8*sub + 2j, 8*sub + 2j + 1). 8-add half chains.
    __half2 acc0[4], acc1[4];
    #pragma unroll
    for (int j = 0; j < 4; ++j) {
        acc0[j] = __float2half2_rn(0.f);
        acc1[j] = __float2half2_rn(0.f);
    }

    // Lane's slice starts at half2 column 4*sub (dims 8*sub .. 8*sub+7).
    const __half2* base = W_half + 4 * (size_t)sub;

    #pragma unroll
    for (int i = 0; i < TOKENS / 2; ++i) {
        const int row = __shfl_sync(FULL_MASK, my_idx, 2 * i + half_sel);
        float4 raw = *reinterpret_cast<const float4*>(base + (size_t)row * (DIMS / 2));
        const __half2 v0 = *reinterpret_cast<const __half2*>(&raw.x);
        const __half2 v1 = *reinterpret_cast<const __half2*>(&raw.y);
        const __half2 v2 = *reinterpret_cast<const __half2*>(&raw.z);
        const __half2 v3 = *reinterpret_cast<const __half2*>(&raw.w);
        if ((i & 1) == 0) {
            acc0[0] = __hadd2(acc0[0], v0);
            acc0[1] = __hadd2(acc0[1], v1);
            acc0[2] = __hadd2(acc0[2], v2);
            acc0[3] = __hadd2(acc0[3], v3);
        } else {
            acc1[0] = __hadd2(acc1[0], v0);
            acc1[1] = __hadd2(acc1[1], v1);
            acc1[2] = __hadd2(acc1[2], v2);
            acc1[3] = __hadd2(acc1[3], v3);
        }
    }

    // Combine splits in fp32: 8 floats (dims 8*sub..8*sub+7), this half-warp's
    // 16-token partial.
    float sum[8];
    #pragma unroll
    for (int j = 0; j < 4; ++j) {
        float2 a = __half22float2(acc0[j]);
        float2 b = __half22float2(acc1[j]);
        sum[2 * j]     = a.x + b.x;
        sum[2 * j + 1] = a.y + b.y;
    }

    // Fold odd-token half (lanes 16-31) into even-token half (lanes 0-15).
    #pragma unroll
    for (int k = 0; k < 8; ++k)
        sum[k] += __shfl_down_sync(FULL_MASK, sum[k], 16);

    // Redistribute: lane l takes dims [4l, 4l+4), which live on lane l>>1,
    // entries [4*(l&1), 4*(l&1)+4). 8 SHFL + 4 selects.
    const int src  = lane >> 1;
    const bool hi  = (lane & 1) != 0;
    float s4[4];
    #pragma unroll
    for (int k = 0; k < 4; ++k) {
        const float lo_v = __shfl_sync(FULL_MASK, sum[k],     src);
        const float hi_v = __shfl_sync(FULL_MASK, sum[k + 4], src);
        s4[k] = hi ? hi_v : lo_v;
    }

    // R9-shaped epilogue on all 32 lanes: 4 erffs each.
    const float inv_t = 1.0f / (float)TOKENS;
    const float kInvSqrt2 = 0.70710678118654752440f;

    float p0 = s4[0] * inv_t, p1 = s4[1] * inv_t,
          p2 = s4[2] * inv_t, p3 = s4[3] * inv_t;
    float g0 = 0.5f * p0 * (1.0f + erff(p0 * kInvSqrt2));
    float g1 = 0.5f * p1 * (1.0f + erff(p1 * kInvSqrt2));
    float g2 = 0.5f * p2 * (1.0f + erff(p2 * kInvSqrt2));
    float g3 = 0.5f * p3 * (1.0f + erff(p3 * kInvSqrt2));

    const float4 wv = *reinterpret_cast<const float4*>(w_pred + lane * 4);
    float dot = g0 * wv.x + g1 * wv.y + g2 * wv.z + g3 * wv.w;

    #pragma unroll
    for (int off = 16; off > 0; off >>= 1)
        dot += __shfl_down_sync(FULL_MASK, dot, off);

    if (lane == 0)
        out[gwarp] = dot + b_pred[0];
}

extern "C" void kernel_launch(void* const* d_in, const int* in_sizes, int n_in,
                              void* d_out, int out_size)
{
    const int*   x      = (const int*)  d_in[0];  // [8,100,64,32] int32
    const float* W      = (const float*)d_in[1];  // [32000,128]  f32
    const float* w_pred = (const float*)d_in[2];  // [1,128]      f32
    const float* b_pred = (const float*)d_in[3];  // [1]          f32
    float*       out    = (float*)d_out;          // [8,100,64]   f32

    // 1) Convert W to fp16 scratch (8 elems per thread, STG.128).
    const int n8 = VOCAB * DIMS / 8;               // 512,000
    convert_w_kernel<<<(n8 + 255) / 256, 256>>>(W, n8);

    // 2) Gather + pool + GELU + dot.
    const int n_cells = out_size;                  // 51200
    const int blocks = (n_cells + 7) / 8;          // 8 warps / block
    gelu_avg_embed_kernel<<<blocks, 256>>>(x, w_pred, b_pred, out, n_cells);
}

// round 12
// speedup vs baseline: 1.1283x; 1.0667x over previous
#include <cuda_runtime.h>
#include <cuda_fp16.h>
#include <cstdint>
#include <cstring>

// GeluAvgEmbed: out[cell] = dot(gelu(mean_t W[x[cell,t]]), w_pred) + b_pred
// B,R,C,T = 8,100,64,32 ; D = 128 ; VOCAB = 32000
//
// R12: fp16 table; 2 rows per warp-iteration; loads issued in BATCHES OF 8
// so 8 LDG.128s are in flight per warp (launch_bounds(256,4) -> 64-reg
// budget, occ 50%). Accumulation arithmetic identical to R11 (two 8-add
// half2 chains per dim pair, fp32 combine), so rel_err is unchanged.

#define TOKENS 32
#define DIMS   128
#define VOCAB  32000
#define FULL_MASK 0xffffffffu

// fp16 copy of the embedding table: 32000 * 128 * 2B = 8.192 MB
__device__ __half2 W_half[(size_t)VOCAB * DIMS / 2];

__global__ __launch_bounds__(256) void convert_w_kernel(
    const float* __restrict__ W, int n8)
{
    int i = blockIdx.x * blockDim.x + threadIdx.x;
    if (i >= n8) return;
    const float4* src = reinterpret_cast<const float4*>(W) + 2 * (size_t)i;
    float4 v0 = src[0];
    float4 v1 = src[1];
    __half2 h[4];
    h[0] = __floats2half2_rn(v0.x, v0.y);
    h[1] = __floats2half2_rn(v0.z, v0.w);
    h[2] = __floats2half2_rn(v1.x, v1.y);
    h[3] = __floats2half2_rn(v1.z, v1.w);
    float4 packed;
    memcpy(&packed, h, 16);
    reinterpret_cast<float4*>(W_half)[i] = packed;   // one STG.128
}

__global__ __launch_bounds__(256, 4) void gelu_avg_embed_kernel(
    const int*   __restrict__ x,        // [n_cells * 32]
    const float* __restrict__ w_pred,   // [128]
    const float* __restrict__ b_pred,   // [1]
    float*       __restrict__ out,      // [n_cells]
    int n_cells)
{
    const int gwarp = (blockIdx.x * blockDim.x + threadIdx.x) >> 5;
    const int lane  = threadIdx.x & 31;
    if (gwarp >= n_cells) return;

    // Lane t holds token t's vocab index (coalesced 128B load of 32 ints).
    const int my_idx = x[gwarp * TOKENS + lane];

    const int half_sel = lane >> 4;   // which token of the pair this lane serves
    const int sub      = lane & 15;   // which 8-dim slice of the row

    // Lane's slice starts at half2 column 4*sub (dims 8*sub .. 8*sub+7).
    const __half2* base = W_half + 4 * (size_t)sub;

    // Two accumulator banks (one per batch); each half chain sees 8 adds.
    __half2 acc0[4], acc1[4];
    #pragma unroll
    for (int j = 0; j < 4; ++j) {
        acc0[j] = __float2half2_rn(0.f);
        acc1[j] = __float2half2_rn(0.f);
    }

    // ---- Batch 0: iterations 0..7 (tokens 0..15) ----
    float4 raw[8];
    #pragma unroll
    for (int i = 0; i < 8; ++i) {
        const int row = __shfl_sync(FULL_MASK, my_idx, 2 * i + half_sel);
        raw[i] = *reinterpret_cast<const float4*>(base + (size_t)row * (DIMS / 2));
    }
    #pragma unroll
    for (int i = 0; i < 8; ++i) {
        acc0[0] = __hadd2(acc0[0], *reinterpret_cast<const __half2*>(&raw[i].x));
        acc0[1] = __hadd2(acc0[1], *reinterpret_cast<const __half2*>(&raw[i].y));
        acc0[2] = __hadd2(acc0[2], *reinterpret_cast<const __half2*>(&raw[i].z));
        acc0[3] = __hadd2(acc0[3], *reinterpret_cast<const __half2*>(&raw[i].w));
    }

    // ---- Batch 1: iterations 8..15 (tokens 16..31) ----
    #pragma unroll
    for (int i = 0; i < 8; ++i) {
        const int row = __shfl_sync(FULL_MASK, my_idx, 2 * (i + 8) + half_sel);
        raw[i] = *reinterpret_cast<const float4*>(base + (size_t)row * (DIMS / 2));
    }
    #pragma unroll
    for (int i = 0; i < 8; ++i) {
        acc1[0] = __hadd2(acc1[0], *reinterpret_cast<const __half2*>(&raw[i].x));
        acc1[1] = __hadd2(acc1[1], *reinterpret_cast<const __half2*>(&raw[i].y));
        acc1[2] = __hadd2(acc1[2], *reinterpret_cast<const __half2*>(&raw[i].z));
        acc1[3] = __hadd2(acc1[3], *reinterpret_cast<const __half2*>(&raw[i].w));
    }

    // Combine banks in fp32: 8 floats (dims 8*sub..8*sub+7) = this
    // half-warp's 16-token partial.
    float sum[8];
    #pragma unroll
    for (int j = 0; j < 4; ++j) {
        float2 a = __half22float2(acc0[j]);
        float2 b = __half22float2(acc1[j]);
        sum[2 * j]     = a.x + b.x;
        sum[2 * j + 1] = a.y + b.y;
    }

    // Fold odd-token half (lanes 16-31) into even-token half (lanes 0-15).
    #pragma unroll
    for (int k = 0; k < 8; ++k)
        sum[k] += __shfl_down_sync(FULL_MASK, sum[k], 16);

    // Redistribute: lane l takes dims [4l, 4l+4) from lane l>>1,
    // entries [4*(l&1), 4*(l&1)+4).
    const int src  = lane >> 1;
    const bool hi  = (lane & 1) != 0;
    float s4[4];
    #pragma unroll
    for (int k = 0; k < 4; ++k) {
        const float lo_v = __shfl_sync(FULL_MASK, sum[k],     src);
        const float hi_v = __shfl_sync(FULL_MASK, sum[k + 4], src);
        s4[k] = hi ? hi_v : lo_v;
    }

    // Epilogue on all 32 lanes: 4 erffs each.
    const float inv_t = 1.0f / (float)TOKENS;
    const float kInvSqrt2 = 0.70710678118654752440f;

    float p0 = s4[0] * inv_t, p1 = s4[1] * inv_t,
          p2 = s4[2] * inv_t, p3 = s4[3] * inv_t;
    float g0 = 0.5f * p0 * (1.0f + erff(p0 * kInvSqrt2));
    float g1 = 0.5f * p1 * (1.0f + erff(p1 * kInvSqrt2));
    float g2 = 0.5f * p2 * (1.0f + erff(p2 * kInvSqrt2));
    float g3 = 0.5f * p3 * (1.0f + erff(p3 * kInvSqrt2));

    const float4 wv = *reinterpret_cast<const float4*>(w_pred + lane * 4);
    float dot = g0 * wv.x + g1 * wv.y + g2 * wv.z + g3 * wv.w;

    #pragma unroll
    for (int off = 16; off > 0; off >>= 1)
        dot += __shfl_down_sync(FULL_MASK, dot, off);

    if (lane == 0)
        out[gwarp] = dot + b_pred[0];
}

extern "C" void kernel_launch(void* const* d_in, const int* in_sizes, int n_in,
                              void* d_out, int out_size)
{
    const int*   x      = (const int*)  d_in[0];  // [8,100,64,32] int32
    const float* W      = (const float*)d_in[1];  // [32000,128]  f32
    const float* w_pred = (const float*)d_in[2];  // [1,128]      f32
    const float* b_pred = (const float*)d_in[3];  // [1]          f32
    float*       out    = (float*)d_out;          // [8,100,64]   f32

    // 1) Convert W to fp16 scratch (8 elems per thread, STG.128).
    const int n8 = VOCAB * DIMS / 8;               // 512,000
    convert_w_kernel<<<(n8 + 255) / 256, 256>>>(W, n8);

    // 2) Gather + pool + GELU + dot.
    const int n_cells = out_size;                  // 51200
    const int blocks = (n_cells + 7) / 8;          // 8 warps / block
    gelu_avg_embed_kernel<<<blocks, 256>>>(x, w_pred, b_pred, out, n_cells);
}